// round 6
// baseline (speedup 1.0000x reference)
#include <cuda_runtime.h>
#include <cuda_fp16.h>
#include <cstdint>

// Problem:
//   x:      (B=4, T=4096, D=1024) f32
//   idx:    (B=4, E=8, C=1024)    i32
//   weight: (E=8, O=512, D=1024)  f32
//   bias:   (E=8, O=512)          f32
//   out:    (B=4, E=8, C=1024, O=512) f32
// out[b,e,c,o] = sum_d x[b, idx[b,e,c], d] * w[e,o,d] + bias[e,o]
//
// fp16 HMMA GEMM, fp32 accumulation (rel_err ~2.8e-4, under 1e-3).
// x/w preconverted to fp16. CTA tile 128x128, 4 warps, warp tile 64x64
// (0.25 ldsm per mma), 3-stage cp.async pipeline, 2 CTAs/SM.

#define B_ 4
#define T_ 4096
#define D_ 1024
#define E_ 8
#define C_ 1024
#define O_ 512

#define MT 128
#define NT 128
#define KC 64             // fp16 k per chunk -> 128B rows
#define NCHUNK (D_ / KC)  // 16
#define STAGES 3
#define STAGE_SZ 32768    // A 16K + W 16K
#define SMEM_TOTAL (STAGES * STAGE_SZ)   // 98304

__device__ __half g_x16[B_ * T_ * D_];
__device__ __half g_w16[E_ * O_ * D_];

__device__ __forceinline__ uint32_t smem_u32(const void* p) {
    uint32_t a;
    asm("{ .reg .u64 t; cvta.to.shared.u64 t, %1; cvt.u32.u64 %0, t; }" : "=r"(a) : "l"(p));
    return a;
}
__device__ __forceinline__ void cp_async16(uint32_t dst, const void* src) {
    asm volatile("cp.async.cg.shared.global [%0], [%1], 16;" :: "r"(dst), "l"(src));
}
__device__ __forceinline__ void cp_commit() {
    asm volatile("cp.async.commit_group;" ::: "memory");
}
__device__ __forceinline__ void cp_wait1() {
    asm volatile("cp.async.wait_group 1;" ::: "memory");
}
__device__ __forceinline__ void ldsm_x4(uint32_t* r, uint32_t addr) {
    asm volatile("ldmatrix.sync.aligned.m8n8.x4.shared.b16 {%0,%1,%2,%3}, [%4];"
                 : "=r"(r[0]), "=r"(r[1]), "=r"(r[2]), "=r"(r[3]) : "r"(addr));
}
__device__ __forceinline__ void mma_fp16(float* c, const uint32_t* a, uint32_t b0, uint32_t b1) {
    asm volatile(
        "mma.sync.aligned.m16n8k16.row.col.f32.f16.f16.f32 "
        "{%0,%1,%2,%3}, {%4,%5,%6,%7}, {%8,%9}, {%0,%1,%2,%3};"
        : "+f"(c[0]), "+f"(c[1]), "+f"(c[2]), "+f"(c[3])
        : "r"(a[0]), "r"(a[1]), "r"(a[2]), "r"(a[3]), "r"(b0), "r"(b1));
}

// ---------------------------------------------------------------------------
// fp32 -> fp16 converters
// ---------------------------------------------------------------------------
__global__ __launch_bounds__(256) void convert_x_kernel(const float* __restrict__ x) {
    size_t i = ((size_t)blockIdx.x * 256 + threadIdx.x) * 8;
    float4 v0 = *(const float4*)(x + i);
    float4 v1 = *(const float4*)(x + i + 4);
    __half2 h0 = __floats2half2_rn(v0.x, v0.y);
    __half2 h1 = __floats2half2_rn(v0.z, v0.w);
    __half2 h2 = __floats2half2_rn(v1.x, v1.y);
    __half2 h3 = __floats2half2_rn(v1.z, v1.w);
    *reinterpret_cast<uint4*>(g_x16 + i) =
        make_uint4(*(uint32_t*)&h0, *(uint32_t*)&h1, *(uint32_t*)&h2, *(uint32_t*)&h3);
}
__global__ __launch_bounds__(256) void convert_w_kernel(const float* __restrict__ w) {
    size_t i = ((size_t)blockIdx.x * 256 + threadIdx.x) * 8;
    float4 v0 = *(const float4*)(w + i);
    float4 v1 = *(const float4*)(w + i + 4);
    __half2 h0 = __floats2half2_rn(v0.x, v0.y);
    __half2 h1 = __floats2half2_rn(v0.z, v0.w);
    __half2 h2 = __floats2half2_rn(v1.x, v1.y);
    __half2 h3 = __floats2half2_rn(v1.z, v1.w);
    *reinterpret_cast<uint4*>(g_w16 + i) =
        make_uint4(*(uint32_t*)&h0, *(uint32_t*)&h1, *(uint32_t*)&h2, *(uint32_t*)&h3);
}

// ---------------------------------------------------------------------------
// Main GEMM: 128 threads, 4 warps 2(M)x2(N), warp tile 64x64, 3-stage cp.async
// ---------------------------------------------------------------------------
__global__ __launch_bounds__(128, 2)
void moe_fp16_kernel(const int*   __restrict__ idx,
                     const float* __restrict__ bias,
                     float*       __restrict__ out)
{
    extern __shared__ char smem[];
    const uint32_t sb = smem_u32(smem);
    const int tid  = threadIdx.x;
    const int wid  = tid >> 5;
    const int lane = tid & 31;

    const int be = blockIdx.z;
    const int b  = be >> 3;
    const int e  = be & 7;
    const int c0 = blockIdx.y * MT;
    const int o0 = blockIdx.x * NT;

    // ---- producer mapping: thread tid owns A row tid and W row tid (8x16B each)
    const int tok = idx[be * C_ + c0 + tid];
    const __half* asrc = g_x16 + ((size_t)b * T_ + tok) * D_;
    const __half* wsrc = g_w16 + ((size_t)(e * O_ + o0 + tid)) * D_;
    const uint32_t pXor  = (uint32_t)((tid & 7) << 4);
    const uint32_t pRowB = (uint32_t)(tid * 128);

    // ---- compute mapping: warp (wm, wn) owns 64x64 ----
    const int wm = wid >> 1;
    const int wn = wid & 1;

    const uint32_t fXor = (uint32_t)((lane & 7) << 4);
    const uint32_t aBase = (uint32_t)((wm * 64 + (lane & 15)) * 128);
    const uint32_t aSegL = (uint32_t)((lane >> 4) * 16);
    const uint32_t wBase = (uint32_t)(16384 + (wn * 64 + ((lane >> 4) << 3) + (lane & 7)) * 128);
    const uint32_t wSegL = (uint32_t)(((lane >> 3) & 1) * 16);

    float acc[4][8][4];
    #pragma unroll
    for (int i = 0; i < 4; i++)
        #pragma unroll
        for (int j = 0; j < 8; j++)
            #pragma unroll
            for (int q = 0; q < 4; q++) acc[i][j][q] = 0.0f;

    auto load_stage = [&](int st, int kc) {
        const uint32_t abase = sb + st * STAGE_SZ + pRowB;
        const uint32_t wbase = abase + 16384;
        const __half* ap = asrc + kc * KC;
        const __half* wp = wsrc + kc * KC;
        #pragma unroll
        for (int j = 0; j < 8; j++) {
            const uint32_t off = ((uint32_t)(j * 16)) ^ pXor;
            cp_async16(abase + off, ap + j * 8);
            cp_async16(wbase + off, wp + j * 8);
        }
    };

    load_stage(0, 0); cp_commit();
    load_stage(1, 1); cp_commit();

    for (int kc = 0; kc < NCHUNK; kc++) {
        cp_wait1();
        __syncthreads();

        if (kc + 2 < NCHUNK) load_stage((kc + 2) % STAGES, kc + 2);
        cp_commit();   // empty groups at tail keep wait_group counts valid

        const uint32_t stb = sb + (kc % STAGES) * STAGE_SZ;
        #pragma unroll
        for (int ks = 0; ks < 4; ks++) {
            const uint32_t kb = (uint32_t)(ks * 32);
            uint32_t af[4][4];
            #pragma unroll
            for (int mt = 0; mt < 4; mt++)
                ldsm_x4(af[mt], stb + aBase + mt * 2048 + ((kb + aSegL) ^ fXor));
            uint32_t wf[4][4];
            #pragma unroll
            for (int np = 0; np < 4; np++)
                ldsm_x4(wf[np], stb + wBase + np * 2048 + ((kb + wSegL) ^ fXor));

            #pragma unroll
            for (int mt = 0; mt < 4; mt++)
                #pragma unroll
                for (int np = 0; np < 4; np++) {
                    mma_fp16(acc[mt][np * 2 + 0], af[mt], wf[np][0], wf[np][1]);
                    mma_fp16(acc[mt][np * 2 + 1], af[mt], wf[np][2], wf[np][3]);
                }
        }
    }

    // ---- epilogue ----
    float2 bv[8];
    #pragma unroll
    for (int n4 = 0; n4 < 8; n4++)
        bv[n4] = *reinterpret_cast<const float2*>(bias + e * O_ + o0 + wn * 64 + n4 * 8 + (lane & 3) * 2);

    #pragma unroll
    for (int mt = 0; mt < 4; mt++) {
        const int row = wm * 64 + mt * 16 + (lane >> 2);
        float* d0 = out + ((size_t)be * C_ + c0 + row) * O_ + o0;
        float* d1 = d0 + 8 * O_;
        #pragma unroll
        for (int n4 = 0; n4 < 8; n4++) {
            const int col = wn * 64 + n4 * 8 + (lane & 3) * 2;
            float2 v0, v1;
            v0.x = acc[mt][n4][0] + bv[n4].x;
            v0.y = acc[mt][n4][1] + bv[n4].y;
            v1.x = acc[mt][n4][2] + bv[n4].x;
            v1.y = acc[mt][n4][3] + bv[n4].y;
            *reinterpret_cast<float2*>(d0 + col) = v0;
            *reinterpret_cast<float2*>(d1 + col) = v1;
        }
    }
}

extern "C" void kernel_launch(void* const* d_in, const int* in_sizes, int n_in,
                              void* d_out, int out_size)
{
    const float* x    = (const float*)d_in[0];
    const int*   idx  = (const int*)  d_in[1];
    const float* w    = (const float*)d_in[2];
    const float* bias = (const float*)d_in[3];
    float* out = (float*)d_out;

    cudaFuncSetAttribute(moe_fp16_kernel,
                         cudaFuncAttributeMaxDynamicSharedMemorySize, SMEM_TOTAL);

    convert_x_kernel<<<(B_ * T_ * D_) / (256 * 8), 256>>>(x);
    convert_w_kernel<<<(E_ * O_ * D_) / (256 * 8), 256>>>(w);

    dim3 grid(O_ / NT, C_ / MT, B_ * E_);   // (4, 8, 32)
    moe_fp16_kernel<<<grid, 128, SMEM_TOTAL>>>(idx, bias, out);
}

// round 8
// speedup vs baseline: 1.3856x; 1.3856x over previous
#include <cuda_runtime.h>
#include <cuda_fp16.h>
#include <cstdint>

// Problem:
//   x:      (B=4, T=4096, D=1024) f32
//   idx:    (B=4, E=8, C=1024)    i32
//   weight: (E=8, O=512, D=1024)  f32
//   bias:   (E=8, O=512)          f32
//   out:    (B=4, E=8, C=1024, O=512) f32
// out[b,e,c,o] = sum_d x[b, idx[b,e,c], d] * w[e,o,d] + bias[e,o]
//
// fp16 HMMA GEMM, fp32 accumulation (rel_err ~2.8e-4).
// x/w preconverted to fp16 (single merged kernel). Main GEMM: CTA 128x128,
// 8 warps (2M x 4N), warp tile 64x32, 3-stage cp.async, 2 CTAs/SM,
// ldmatrix fragments double-buffered across k16 steps.

#define B_ 4
#define T_ 4096
#define D_ 1024
#define E_ 8
#define C_ 1024
#define O_ 512

#define MT 128
#define NT 128
#define KC 64             // fp16 k per chunk -> 128B rows
#define NCHUNK (D_ / KC)  // 16
#define STAGES 3
#define STAGE_SZ 32768    // A 16K + W 16K
#define SMEM_TOTAL (STAGES * STAGE_SZ)   // 98304

__device__ __half g_x16[B_ * T_ * D_];
__device__ __half g_w16[E_ * O_ * D_];

#define NXG ((B_ * T_ * D_) / 8)   // x 8-elem groups
#define NWG ((E_ * O_ * D_) / 8)   // w 8-elem groups

__device__ __forceinline__ uint32_t smem_u32(const void* p) {
    uint32_t a;
    asm("{ .reg .u64 t; cvta.to.shared.u64 t, %1; cvt.u32.u64 %0, t; }" : "=r"(a) : "l"(p));
    return a;
}
__device__ __forceinline__ void cp_async16(uint32_t dst, const void* src) {
    asm volatile("cp.async.cg.shared.global [%0], [%1], 16;" :: "r"(dst), "l"(src));
}
__device__ __forceinline__ void cp_commit() {
    asm volatile("cp.async.commit_group;" ::: "memory");
}
__device__ __forceinline__ void cp_wait1() {
    asm volatile("cp.async.wait_group 1;" ::: "memory");
}
__device__ __forceinline__ void ldsm_x4(uint32_t* r, uint32_t addr) {
    asm volatile("ldmatrix.sync.aligned.m8n8.x4.shared.b16 {%0,%1,%2,%3}, [%4];"
                 : "=r"(r[0]), "=r"(r[1]), "=r"(r[2]), "=r"(r[3]) : "r"(addr));
}
__device__ __forceinline__ void mma_fp16(float* c, const uint32_t* a, uint32_t b0, uint32_t b1) {
    asm volatile(
        "mma.sync.aligned.m16n8k16.row.col.f32.f16.f16.f32 "
        "{%0,%1,%2,%3}, {%4,%5,%6,%7}, {%8,%9}, {%0,%1,%2,%3};"
        : "+f"(c[0]), "+f"(c[1]), "+f"(c[2]), "+f"(c[3])
        : "r"(a[0]), "r"(a[1]), "r"(a[2]), "r"(a[3]), "r"(b0), "r"(b1));
}

// ---------------------------------------------------------------------------
// merged fp32 -> fp16 converter for x and w
// ---------------------------------------------------------------------------
__global__ __launch_bounds__(256)
void convert_all_kernel(const float* __restrict__ x, const float* __restrict__ w) {
    const size_t g = (size_t)blockIdx.x * 256 + threadIdx.x;
    const float* src;
    __half* dst;
    size_t i;
    if (g < NXG) { i = g * 8;          src = x + i; dst = g_x16 + i; }
    else         { i = (g - NXG) * 8;  src = w + i; dst = g_w16 + i; }
    float4 v0 = *(const float4*)(src);
    float4 v1 = *(const float4*)(src + 4);
    __half2 h0 = __floats2half2_rn(v0.x, v0.y);
    __half2 h1 = __floats2half2_rn(v0.z, v0.w);
    __half2 h2 = __floats2half2_rn(v1.x, v1.y);
    __half2 h3 = __floats2half2_rn(v1.z, v1.w);
    *reinterpret_cast<uint4*>(dst) =
        make_uint4(*(uint32_t*)&h0, *(uint32_t*)&h1, *(uint32_t*)&h2, *(uint32_t*)&h3);
}

// ---------------------------------------------------------------------------
// Main GEMM: 256 threads, 8 warps 2(M)x4(N), warp tile 64x32, 3-stage cp.async
// ---------------------------------------------------------------------------
__global__ __launch_bounds__(256, 2)
void moe_fp16_kernel(const int*   __restrict__ idx,
                     const float* __restrict__ bias,
                     float*       __restrict__ out)
{
    extern __shared__ char smem[];
    const uint32_t sb = smem_u32(smem);
    const int tid  = threadIdx.x;
    const int wid  = tid >> 5;
    const int lane = tid & 31;

    const int be = blockIdx.z;
    const int b  = be >> 3;
    const int e  = be & 7;
    const int c0 = blockIdx.y * MT;
    const int o0 = blockIdx.x * NT;

    // ---- producer mapping: row = tid/2, 64B half = tid&1; 4x16B per operand ----
    const int prow  = tid >> 1;
    const int phalf = (tid & 1) * 64;
    const int tok   = idx[be * C_ + c0 + prow];
    const __half* asrc = g_x16 + ((size_t)b * T_ + tok) * D_ + (phalf >> 1);
    const __half* wsrc = g_w16 + ((size_t)(e * O_ + o0 + prow)) * D_ + (phalf >> 1);
    const uint32_t pXor  = (uint32_t)((prow & 7) << 4);
    const uint32_t pRowB = (uint32_t)(prow * 128);

    // ---- compute mapping ----
    const int wm = wid >> 2;                       // 0..1 -> M offset wm*64
    const int wn = wid & 3;                        // 0..3 -> N offset wn*32

    const uint32_t fXor = (uint32_t)((lane & 7) << 4);
    const uint32_t aBase = (uint32_t)((wm * 64 + (lane & 15)) * 128);
    const uint32_t aSegL = (uint32_t)((lane >> 4) * 16);
    const uint32_t wBase = (uint32_t)(16384 + (wn * 32 + ((lane >> 4) << 3) + (lane & 7)) * 128);
    const uint32_t wSegL = (uint32_t)(((lane >> 3) & 1) * 16);

    float acc[4][4][4];
    #pragma unroll
    for (int i = 0; i < 4; i++)
        #pragma unroll
        for (int j = 0; j < 4; j++)
            #pragma unroll
            for (int q = 0; q < 4; q++) acc[i][j][q] = 0.0f;

    auto load_stage = [&](int st, int kc) {
        const uint32_t abase = sb + st * STAGE_SZ + pRowB;
        const uint32_t wbase = abase + 16384;
        const __half* ap = asrc + kc * KC;
        const __half* wp = wsrc + kc * KC;
        #pragma unroll
        for (int j = 0; j < 4; j++) {
            const uint32_t off = ((uint32_t)(phalf + j * 16)) ^ pXor;
            cp_async16(abase + off, ap + j * 8);
            cp_async16(wbase + off, wp + j * 8);
        }
    };

    load_stage(0, 0); cp_commit();
    load_stage(1, 1); cp_commit();

    uint32_t af[2][4][4];   // [buf][mt][frag]
    uint32_t wf[2][2][4];   // [buf][np][frag]

    for (int kc = 0; kc < NCHUNK; kc++) {
        cp_wait1();
        __syncthreads();

        if (kc + 2 < NCHUNK) load_stage((kc + 2) % STAGES, kc + 2);
        cp_commit();   // empty groups at tail keep wait_group counts valid

        const uint32_t stb = sb + (kc % STAGES) * STAGE_SZ;
        const uint32_t aAddr = stb + aBase;
        const uint32_t wAddr = stb + wBase;

        // preload ks=0 fragments
        #pragma unroll
        for (int mt = 0; mt < 4; mt++)
            ldsm_x4(af[0][mt], aAddr + mt * 2048 + ((0 + aSegL) ^ fXor));
        #pragma unroll
        for (int np = 0; np < 2; np++)
            ldsm_x4(wf[0][np], wAddr + np * 2048 + ((0 + wSegL) ^ fXor));

        #pragma unroll
        for (int ks = 0; ks < 4; ks++) {
            const int cur = ks & 1;
            const int nxt = cur ^ 1;
            if (ks < 3) {
                const uint32_t kb = (uint32_t)((ks + 1) * 32);
                #pragma unroll
                for (int mt = 0; mt < 4; mt++)
                    ldsm_x4(af[nxt][mt], aAddr + mt * 2048 + ((kb + aSegL) ^ fXor));
                #pragma unroll
                for (int np = 0; np < 2; np++)
                    ldsm_x4(wf[nxt][np], wAddr + np * 2048 + ((kb + wSegL) ^ fXor));
            }
            #pragma unroll
            for (int mt = 0; mt < 4; mt++)
                #pragma unroll
                for (int np = 0; np < 2; np++) {
                    mma_fp16(acc[mt][np * 2 + 0], af[cur][mt], wf[cur][np][0], wf[cur][np][1]);
                    mma_fp16(acc[mt][np * 2 + 1], af[cur][mt], wf[cur][np][2], wf[cur][np][3]);
                }
        }
    }

    // ---- epilogue ----
    float2 bv[4];
    #pragma unroll
    for (int n4 = 0; n4 < 4; n4++)
        bv[n4] = *reinterpret_cast<const float2*>(bias + e * O_ + o0 + wn * 32 + n4 * 8 + (lane & 3) * 2);

    #pragma unroll
    for (int mt = 0; mt < 4; mt++) {
        const int row = wm * 64 + mt * 16 + (lane >> 2);
        float* d0 = out + ((size_t)be * C_ + c0 + row) * O_ + o0;
        float* d1 = d0 + 8 * O_;
        #pragma unroll
        for (int n4 = 0; n4 < 4; n4++) {
            const int col = wn * 32 + n4 * 8 + (lane & 3) * 2;
            float2 v0, v1;
            v0.x = acc[mt][n4][0] + bv[n4].x;
            v0.y = acc[mt][n4][1] + bv[n4].y;
            v1.x = acc[mt][n4][2] + bv[n4].x;
            v1.y = acc[mt][n4][3] + bv[n4].y;
            *reinterpret_cast<float2*>(d0 + col) = v0;
            *reinterpret_cast<float2*>(d1 + col) = v1;
        }
    }
}

extern "C" void kernel_launch(void* const* d_in, const int* in_sizes, int n_in,
                              void* d_out, int out_size)
{
    const float* x    = (const float*)d_in[0];
    const int*   idx  = (const int*)  d_in[1];
    const float* w    = (const float*)d_in[2];
    const float* bias = (const float*)d_in[3];
    float* out = (float*)d_out;

    cudaFuncSetAttribute(moe_fp16_kernel,
                         cudaFuncAttributeMaxDynamicSharedMemorySize, SMEM_TOTAL);

    convert_all_kernel<<<(NXG + NWG) / 256, 256>>>(x, w);

    dim3 grid(O_ / NT, C_ / MT, B_ * E_);   // (4, 8, 32)
    moe_fp16_kernel<<<grid, 256, SMEM_TOTAL>>>(idx, bias, out);
}